// round 16
// baseline (speedup 1.0000x reference)
#include <cuda_runtime.h>
#include <cstdint>

// Problem constants
constexpr int B_ = 8;
constexpr int S_ = 4096;
constexpr int D_ = 2048;
constexpr int R_ = 4;
// Effective math: out[b,s,:] = relu(0.25 * (x[b,s,:] @ Bc_b) @ Ac_b),
// Bc_b = concat(adapter_b[4b..4b+3]) -> [2048,16], Ac_b -> [16,2048].

constexpr int THREADS = 256;  // 8 warps x m16 tiles = 128 rows
constexpr int TILE_M = 128;
constexpr int KSLAB = 64;            // 32 bf16x2 pairs per row per slab
constexpr int NSLAB = D_ / KSLAB;    // 32
constexpr int XS_STR = 36;           // u32 stride; bank = (4*row + col) % 32
constexpr int BS_STR = 40;           // u32 stride; bank = (8*kp + n) % 32

// ============================ helpers ============================
// pack high-16 bits (bf16 truncation) of two floats: low half = a, high = b
__device__ __forceinline__ uint32_t bfpack_hi(float a, float b) {
    uint32_t r;
    asm("prmt.b32 %0, %1, %2, 0x7632;"
        : "=r"(r) : "r"(__float_as_uint(a)), "r"(__float_as_uint(b)));
    return r;
}
// round-to-nearest bf16x2 pack: low half = a, high = b
__device__ __forceinline__ uint32_t bfpack_rn(float a, float b) {
    uint32_t r;
    asm("cvt.rn.bf16x2.f32 %0, %1, %2;" : "=r"(r) : "f"(b), "f"(a));
    return r;
}
__device__ __forceinline__ float bflo_f(uint32_t p) {
    return __uint_as_float(p << 16);
}
__device__ __forceinline__ float bfhi_f(uint32_t p) {
    return __uint_as_float(p & 0xffff0000u);
}
__device__ __forceinline__ void mma_bf16(float c[4], uint32_t a0, uint32_t a1,
                                         uint32_t a2, uint32_t a3, uint32_t b0,
                                         uint32_t b1) {
    asm volatile(
        "mma.sync.aligned.m16n8k16.row.col.f32.bf16.bf16.f32 "
        "{%0,%1,%2,%3}, {%4,%5,%6,%7}, {%8,%9}, {%0,%1,%2,%3};"
        : "+f"(c[0]), "+f"(c[1]), "+f"(c[2]), "+f"(c[3])
        : "r"(a0), "r"(a1), "r"(a2), "r"(a3), "r"(b0), "r"(b1));
}
// ---- packed f32x2 helpers ----
__device__ __forceinline__ unsigned long long fma2(unsigned long long a,
                                                   unsigned long long b,
                                                   unsigned long long c) {
    unsigned long long d;
    asm("fma.rn.f32x2 %0, %1, %2, %3;" : "=l"(d) : "l"(a), "l"(b), "l"(c));
    return d;
}
__device__ __forceinline__ unsigned long long add2(unsigned long long a,
                                                   unsigned long long b) {
    unsigned long long d;
    asm("add.rn.f32x2 %0, %1, %2;" : "=l"(d) : "l"(a), "l"(b));
    return d;
}
__device__ __forceinline__ unsigned long long pack2(float lo, float hi) {
    unsigned long long d;
    asm("mov.b64 %0, {%1, %2};" : "=l"(d) : "f"(lo), "f"(hi));
    return d;
}
__device__ __forceinline__ float2 unpack2(unsigned long long v) {
    float2 r;
    asm("mov.b64 {%0, %1}, %2;" : "=f"(r.x), "=f"(r.y) : "l"(v));
    return r;
}

// ============================================================================
// Fused LoRA kernel. Per CTA: 128 rows of one batch.
// Phase 1 (tensor): h_tile = X_tile @ Bc_b via mma.sync m16n8k16 bf16,
//   3-pass hi/lo split (err ~2^-16); C frags stored scaled by 0.25 into
//   smem hsf[128][16]. h never touches gmem.
// Phase 2 (stream): out[row][d] = relu(sum_c hsf[row][c] * Ac[c][d]) for the
//   same 128 rows, 2 column halves of 1024; A slice in regs, h via scalar
//   LDS broadcasts, STG.128 writes.
// Cross-CTA desync overlaps phase-1 (LDS/tensor) with phase-2 (DRAM write).
// ============================================================================
__global__ __launch_bounds__(THREADS) void lora_fused(
    const float* __restrict__ x, const float* __restrict__ ab,
    const float* __restrict__ aa, float* __restrict__ out) {
    __shared__ uint32_t xh[TILE_M * XS_STR];  // 18432 B
    __shared__ uint32_t xl[TILE_M * XS_STR];  // 18432 B
    __shared__ uint32_t bh[32 * BS_STR];      // 5120 B
    __shared__ uint32_t bl[32 * BS_STR];      // 5120 B
    __shared__ float hsf[TILE_M * 16];        // 8192 B

    const int tid = threadIdx.x;
    const int w = tid >> 5;
    const int lane = tid & 31;
    const int g = lane >> 2;  // frag row / n
    const int tg = lane & 3;  // frag k sub-index
    const int row0 = blockIdx.x * TILE_M;
    const int b = blockIdx.x >> 5;  // 32 CTAs per batch

    // B loader mapping: thread -> (kp = t>>4 (+16/iter), n = t&15)
    const int bkp = tid >> 4;
    const int bn = tid & 15;
    const float* bsrc0 =
        ab + ((size_t)(4 * b + (bn >> 2)) * D_) * R_ + (bn & 3);

    float acc[2][4];
#pragma unroll
    for (int nt = 0; nt < 2; nt++)
#pragma unroll
        for (int i = 0; i < 4; i++) acc[nt][i] = 0.0f;

    // ---- prefetch slab 0 ----
    float4 xv[8];
    float be[2][2];
#pragma unroll
    for (int i = 0; i < 8; i++) {
        const int f = i * 256 + tid;
        xv[i] = *(const float4*)(x + (size_t)(row0 + (f >> 4)) * D_ +
                                 (f & 15) * 4);
    }
#pragma unroll
    for (int it = 0; it < 2; it++) {
        const int k = 2 * (bkp + it * 16);
        be[it][0] = bsrc0[(size_t)k * R_];
        be[it][1] = bsrc0[(size_t)(k + 1) * R_];
    }

    for (int t = 0; t < NSLAB; t++) {
        __syncthreads();  // previous slab's compute done
        // ---- stage x hi/lo (bf16 pairs, parity-XOR swizzle) ----
#pragma unroll
        for (int i = 0; i < 8; i++) {
            const int f = i * 256 + tid;
            const int r = f >> 4;
            const int kq = f & 15;
            const float4 v = xv[i];
            const uint32_t h0 = bfpack_hi(v.x, v.y);
            const uint32_t h1 = bfpack_hi(v.z, v.w);
            const uint32_t l0 =
                bfpack_rn(v.x - bflo_f(h0), v.y - bfhi_f(h0));
            const uint32_t l1 =
                bfpack_rn(v.z - bflo_f(h1), v.w - bfhi_f(h1));
            const int par = r & 1;
            const int base = r * XS_STR;
            xh[base + ((2 * kq) ^ par)] = h0;
            xh[base + ((2 * kq + 1) ^ par)] = h1;
            xl[base + ((2 * kq) ^ par)] = l0;
            xl[base + ((2 * kq + 1) ^ par)] = l1;
        }
        // ---- stage B hi/lo ----
#pragma unroll
        for (int it = 0; it < 2; it++) {
            const int kp = bkp + it * 16;
            const float e0 = be[it][0];
            const float e1 = be[it][1];
            const uint32_t h = bfpack_hi(e0, e1);
            const uint32_t l = bfpack_rn(e0 - bflo_f(h), e1 - bfhi_f(h));
            bh[kp * BS_STR + bn] = h;
            bl[kp * BS_STR + bn] = l;
        }
        __syncthreads();

        // ---- prefetch slab t+1 ----
        if (t + 1 < NSLAB) {
            const int kb = (t + 1) * KSLAB;
#pragma unroll
            for (int i = 0; i < 8; i++) {
                const int f = i * 256 + tid;
                xv[i] = *(const float4*)(x + (size_t)(row0 + (f >> 4)) * D_ +
                                         kb + (f & 15) * 4);
            }
#pragma unroll
            for (int it = 0; it < 2; it++) {
                const int k = kb + 2 * (bkp + it * 16);
                be[it][0] = bsrc0[(size_t)k * R_];
                be[it][1] = bsrc0[(size_t)(k + 1) * R_];
            }
        }

        // ---- compute: 4 k16-steps, 2 n-tiles, 3 passes ----
        const int r0 = w * 16 + g;
        const int par = g & 1;
        const uint32_t* xh0 = &xh[r0 * XS_STR];
        const uint32_t* xh1 = &xh[(r0 + 8) * XS_STR];
        const uint32_t* xl0 = &xl[r0 * XS_STR];
        const uint32_t* xl1 = &xl[(r0 + 8) * XS_STR];
#pragma unroll
        for (int ks = 0; ks < 4; ks++) {
            const int p0 = (ks * 8 + tg) ^ par;
            const int p1 = (ks * 8 + tg + 4) ^ par;
            const uint32_t ah0 = xh0[p0], ah1 = xh1[p0];
            const uint32_t ah2 = xh0[p1], ah3 = xh1[p1];
            const uint32_t al0 = xl0[p0], al1 = xl1[p0];
            const uint32_t al2 = xl0[p1], al3 = xl1[p1];
            const int q0 = ks * 8 + tg;
            const int q1 = q0 + 4;
#pragma unroll
            for (int nt = 0; nt < 2; nt++) {
                const int n0 = nt * 8 + g;
                const uint32_t bh0 = bh[q0 * BS_STR + n0];
                const uint32_t bh1 = bh[q1 * BS_STR + n0];
                mma_bf16(acc[nt], ah0, ah1, ah2, ah3, bh0, bh1);
                const uint32_t bl0 = bl[q0 * BS_STR + n0];
                const uint32_t bl1 = bl[q1 * BS_STR + n0];
                mma_bf16(acc[nt], ah0, ah1, ah2, ah3, bl0, bl1);
                mma_bf16(acc[nt], al0, al1, al2, al3, bh0, bh1);
            }
        }
    }

    // ---- store C frags (scaled 0.25) to hsf: rows (g, g+8), cols nt*8+2tg ----
#pragma unroll
    for (int nt = 0; nt < 2; nt++) {
        const int col = nt * 8 + 2 * tg;
        float* o0 = &hsf[(w * 16 + g) * 16 + col];
        o0[0] = acc[nt][0] * 0.25f;
        o0[1] = acc[nt][1] * 0.25f;
        float* o1 = &hsf[(w * 16 + g + 8) * 16 + col];
        o1[0] = acc[nt][2] * 0.25f;
        o1[1] = acc[nt][3] * 0.25f;
    }
    __syncthreads();

    // ======================= Phase 2: out = relu(h @ Ac) =====================
#pragma unroll
    for (int half = 0; half < 2; half++) {
        const int d0 = half * 1024 + tid * 4;

        // A slice into registers: 16 c x 4 d -> 16 x 2 f32x2
        unsigned long long areg[16][2];
#pragma unroll
        for (int j = 0; j < 4; j++) {
#pragma unroll
            for (int r = 0; r < 4; r++) {
                float4 v =
                    *(const float4*)(aa + (size_t)(4 * b + j) * (R_ * D_) +
                                     (size_t)r * D_ + d0);
                areg[j * 4 + r][0] = pack2(v.x, v.y);
                areg[j * 4 + r][1] = pack2(v.z, v.w);
            }
        }

        float* obase = out + (size_t)row0 * D_ + d0;
        for (int rr = 0; rr < TILE_M; rr++) {
            const float* hrow = &hsf[rr * 16];
            unsigned long long a0 = 0ull, a1 = 0ull, a2 = 0ull, a3 = 0ull;
#pragma unroll
            for (int c = 0; c < 16; c += 2) {
                const float h0 = hrow[c];
                const float h1 = hrow[c + 1];
                const unsigned long long hp0 = pack2(h0, h0);
                const unsigned long long hp1 = pack2(h1, h1);
                a0 = fma2(hp0, areg[c + 0][0], a0);
                a1 = fma2(hp0, areg[c + 0][1], a1);
                a2 = fma2(hp1, areg[c + 1][0], a2);
                a3 = fma2(hp1, areg[c + 1][1], a3);
            }
            const unsigned long long s01 = add2(a0, a2);
            const unsigned long long s23 = add2(a1, a3);
            float2 v0 = unpack2(s01);
            float2 v1 = unpack2(s23);
            float4 o;
            o.x = fmaxf(v0.x, 0.0f);
            o.y = fmaxf(v0.y, 0.0f);
            o.z = fmaxf(v1.x, 0.0f);
            o.w = fmaxf(v1.y, 0.0f);
            *(float4*)(obase + (size_t)rr * D_) = o;
        }
    }
}

extern "C" void kernel_launch(void* const* d_in, const int* in_sizes, int n_in,
                              void* d_out, int out_size) {
    const float* x = (const float*)d_in[0];
    const float* ab = (const float*)d_in[1];
    const float* aa = (const float*)d_in[2];
    float* out = (float*)d_out;

    lora_fused<<<(B_ * S_) / TILE_M, THREADS>>>(x, ab, aa, out);
}

// round 17
// speedup vs baseline: 1.0185x; 1.0185x over previous
#include <cuda_runtime.h>
#include <cstdint>

// Problem constants
constexpr int B_ = 8;
constexpr int S_ = 4096;
constexpr int D_ = 2048;
constexpr int R_ = 4;
// Effective math: out[b,s,:] = relu(0.25 * (x[b,s,:] @ Bc_b) @ Ac_b),
// Bc_b = concat(adapter_b[4b..4b+3]) -> [2048,16], Ac_b -> [16,2048].

constexpr int THREADS = 128;  // 4 warps x m16 tiles = 64 rows
constexpr int TILE_M = 64;
constexpr int KSLAB = 64;            // 32 bf16x2 pairs per row per slab
constexpr int NSLAB = D_ / KSLAB;    // 32
constexpr int XS_STR = 36;           // u32 stride; bank = (4*row + col) % 32
constexpr int BS_STR = 40;           // u32 stride; bank = (8*kp + n) % 32

// ============================ helpers ============================
// pack high-16 bits (bf16 truncation) of two floats: low half = a, high = b
__device__ __forceinline__ uint32_t bfpack_hi(float a, float b) {
    uint32_t r;
    asm("prmt.b32 %0, %1, %2, 0x7632;"
        : "=r"(r) : "r"(__float_as_uint(a)), "r"(__float_as_uint(b)));
    return r;
}
// round-to-nearest bf16x2 pack: low half = a, high = b
__device__ __forceinline__ uint32_t bfpack_rn(float a, float b) {
    uint32_t r;
    asm("cvt.rn.bf16x2.f32 %0, %1, %2;" : "=r"(r) : "f"(b), "f"(a));
    return r;
}
__device__ __forceinline__ float bflo_f(uint32_t p) {
    return __uint_as_float(p << 16);
}
__device__ __forceinline__ float bfhi_f(uint32_t p) {
    return __uint_as_float(p & 0xffff0000u);
}
__device__ __forceinline__ void mma_bf16(float c[4], uint32_t a0, uint32_t a1,
                                         uint32_t a2, uint32_t a3, uint32_t b0,
                                         uint32_t b1) {
    asm volatile(
        "mma.sync.aligned.m16n8k16.row.col.f32.bf16.bf16.f32 "
        "{%0,%1,%2,%3}, {%4,%5,%6,%7}, {%8,%9}, {%0,%1,%2,%3};"
        : "+f"(c[0]), "+f"(c[1]), "+f"(c[2]), "+f"(c[3])
        : "r"(a0), "r"(a1), "r"(a2), "r"(a3), "r"(b0), "r"(b1));
}
// ---- packed f32x2 helpers ----
__device__ __forceinline__ unsigned long long fma2(unsigned long long a,
                                                   unsigned long long b,
                                                   unsigned long long c) {
    unsigned long long d;
    asm("fma.rn.f32x2 %0, %1, %2, %3;" : "=l"(d) : "l"(a), "l"(b), "l"(c));
    return d;
}
__device__ __forceinline__ unsigned long long add2(unsigned long long a,
                                                   unsigned long long b) {
    unsigned long long d;
    asm("add.rn.f32x2 %0, %1, %2;" : "=l"(d) : "l"(a), "l"(b));
    return d;
}
__device__ __forceinline__ unsigned long long pack2(float lo, float hi) {
    unsigned long long d;
    asm("mov.b64 %0, {%1, %2};" : "=l"(d) : "f"(lo), "f"(hi));
    return d;
}
__device__ __forceinline__ float2 unpack2(unsigned long long v) {
    float2 r;
    asm("mov.b64 {%0, %1}, %2;" : "=f"(r.x), "=f"(r.y) : "l"(v));
    return r;
}

// ============================================================================
// Fused LoRA kernel, fine-grained: 64 rows per CTA, 128 threads, 512 CTAs
// -> 4 CTAs resident per SM; independent CTAs interleave the tensor/LDS
// phase with the DRAM-write phase, overlapping read and write streams.
// Phase 1: h_tile = X_tile @ Bc_b (mma.sync m16n8k16 bf16, 3-pass hi/lo,
//   err ~2^-16); C frags scaled by 0.25 into smem hsf[64][16].
// Phase 2: out = relu(hsf @ Ac) for the same rows, 4 column quarters of 512.
// ============================================================================
__global__ __launch_bounds__(THREADS, 4) void lora_fused(
    const float* __restrict__ x, const float* __restrict__ ab,
    const float* __restrict__ aa, float* __restrict__ out) {
    __shared__ uint32_t xh[TILE_M * XS_STR];  // 9216 B
    __shared__ uint32_t xl[TILE_M * XS_STR];  // 9216 B
    __shared__ uint32_t bh[32 * BS_STR];      // 5120 B
    __shared__ uint32_t bl[32 * BS_STR];      // 5120 B
    __shared__ float hsf[TILE_M * 16];        // 4096 B

    const int tid = threadIdx.x;
    const int w = tid >> 5;   // 0..3
    const int lane = tid & 31;
    const int g = lane >> 2;  // frag row / n
    const int tg = lane & 3;  // frag k sub-index
    const int row0 = blockIdx.x * TILE_M;
    const int b = blockIdx.x >> 6;  // 64 CTAs per batch

    // B loader mapping: thread -> (kp = tid>>4 (+8/iter), n = tid&15)
    const int bkp = tid >> 4;  // 0..7
    const int bn = tid & 15;
    const float* bsrc0 =
        ab + ((size_t)(4 * b + (bn >> 2)) * D_) * R_ + (bn & 3);

    float acc[2][4];
#pragma unroll
    for (int nt = 0; nt < 2; nt++)
#pragma unroll
        for (int i = 0; i < 4; i++) acc[nt][i] = 0.0f;

    // ---- prefetch slab 0 ----
    float4 xv[8];
    float be[4][2];
#pragma unroll
    for (int i = 0; i < 8; i++) {
        const int f = i * 128 + tid;  // 1024 float4 per slab
        xv[i] = *(const float4*)(x + (size_t)(row0 + (f >> 4)) * D_ +
                                 (f & 15) * 4);
    }
#pragma unroll
    for (int it = 0; it < 4; it++) {
        const int k = 2 * (bkp + it * 8);
        be[it][0] = bsrc0[(size_t)k * R_];
        be[it][1] = bsrc0[(size_t)(k + 1) * R_];
    }

    for (int t = 0; t < NSLAB; t++) {
        __syncthreads();  // previous slab's compute done
        // ---- stage x hi/lo (bf16 pairs, parity-XOR swizzle) ----
#pragma unroll
        for (int i = 0; i < 8; i++) {
            const int f = i * 128 + tid;
            const int r = f >> 4;
            const int kq = f & 15;
            const float4 v = xv[i];
            const uint32_t h0 = bfpack_hi(v.x, v.y);
            const uint32_t h1 = bfpack_hi(v.z, v.w);
            const uint32_t l0 =
                bfpack_rn(v.x - bflo_f(h0), v.y - bfhi_f(h0));
            const uint32_t l1 =
                bfpack_rn(v.z - bflo_f(h1), v.w - bfhi_f(h1));
            const int par = r & 1;
            const int base = r * XS_STR;
            xh[base + ((2 * kq) ^ par)] = h0;
            xh[base + ((2 * kq + 1) ^ par)] = h1;
            xl[base + ((2 * kq) ^ par)] = l0;
            xl[base + ((2 * kq + 1) ^ par)] = l1;
        }
        // ---- stage B hi/lo ----
#pragma unroll
        for (int it = 0; it < 4; it++) {
            const int kp = bkp + it * 8;
            const float e0 = be[it][0];
            const float e1 = be[it][1];
            const uint32_t h = bfpack_hi(e0, e1);
            const uint32_t l = bfpack_rn(e0 - bflo_f(h), e1 - bfhi_f(h));
            bh[kp * BS_STR + bn] = h;
            bl[kp * BS_STR + bn] = l;
        }
        __syncthreads();

        // ---- prefetch slab t+1 ----
        if (t + 1 < NSLAB) {
            const int kb = (t + 1) * KSLAB;
#pragma unroll
            for (int i = 0; i < 8; i++) {
                const int f = i * 128 + tid;
                xv[i] = *(const float4*)(x + (size_t)(row0 + (f >> 4)) * D_ +
                                         kb + (f & 15) * 4);
            }
#pragma unroll
            for (int it = 0; it < 4; it++) {
                const int k = kb + 2 * (bkp + it * 8);
                be[it][0] = bsrc0[(size_t)k * R_];
                be[it][1] = bsrc0[(size_t)(k + 1) * R_];
            }
        }

        // ---- compute: 4 k16-steps, 2 n-tiles, 3 passes ----
        const int r0 = w * 16 + g;
        const int par = g & 1;
        const uint32_t* xh0 = &xh[r0 * XS_STR];
        const uint32_t* xh1 = &xh[(r0 + 8) * XS_STR];
        const uint32_t* xl0 = &xl[r0 * XS_STR];
        const uint32_t* xl1 = &xl[(r0 + 8) * XS_STR];
#pragma unroll
        for (int ks = 0; ks < 4; ks++) {
            const int p0 = (ks * 8 + tg) ^ par;
            const int p1 = (ks * 8 + tg + 4) ^ par;
            const uint32_t ah0 = xh0[p0], ah1 = xh1[p0];
            const uint32_t ah2 = xh0[p1], ah3 = xh1[p1];
            const uint32_t al0 = xl0[p0], al1 = xl1[p0];
            const uint32_t al2 = xl0[p1], al3 = xl1[p1];
            const int q0 = ks * 8 + tg;
            const int q1 = q0 + 4;
#pragma unroll
            for (int nt = 0; nt < 2; nt++) {
                const int n0 = nt * 8 + g;
                const uint32_t bh0 = bh[q0 * BS_STR + n0];
                const uint32_t bh1 = bh[q1 * BS_STR + n0];
                mma_bf16(acc[nt], ah0, ah1, ah2, ah3, bh0, bh1);
                const uint32_t bl0 = bl[q0 * BS_STR + n0];
                const uint32_t bl1 = bl[q1 * BS_STR + n0];
                mma_bf16(acc[nt], ah0, ah1, ah2, ah3, bl0, bl1);
                mma_bf16(acc[nt], al0, al1, al2, al3, bh0, bh1);
            }
        }
    }

    // ---- store C frags (scaled 0.25) to hsf ----
#pragma unroll
    for (int nt = 0; nt < 2; nt++) {
        const int col = nt * 8 + 2 * tg;
        float* o0 = &hsf[(w * 16 + g) * 16 + col];
        o0[0] = acc[nt][0] * 0.25f;
        o0[1] = acc[nt][1] * 0.25f;
        float* o1 = &hsf[(w * 16 + g + 8) * 16 + col];
        o1[0] = acc[nt][2] * 0.25f;
        o1[1] = acc[nt][3] * 0.25f;
    }
    __syncthreads();

    // ======================= Phase 2: out = relu(h @ Ac) =====================
#pragma unroll
    for (int quarter = 0; quarter < 4; quarter++) {
        const int d0 = quarter * 512 + tid * 4;

        // A slice into registers: 16 c x 4 d -> 16 x 2 f32x2
        unsigned long long areg[16][2];
#pragma unroll
        for (int j = 0; j < 4; j++) {
#pragma unroll
            for (int r = 0; r < 4; r++) {
                float4 v =
                    *(const float4*)(aa + (size_t)(4 * b + j) * (R_ * D_) +
                                     (size_t)r * D_ + d0);
                areg[j * 4 + r][0] = pack2(v.x, v.y);
                areg[j * 4 + r][1] = pack2(v.z, v.w);
            }
        }

        float* obase = out + (size_t)row0 * D_ + d0;
        for (int rr = 0; rr < TILE_M; rr++) {
            const float* hrow = &hsf[rr * 16];
            unsigned long long a0 = 0ull, a1 = 0ull, a2 = 0ull, a3 = 0ull;
#pragma unroll
            for (int c = 0; c < 16; c += 2) {
                const float h0 = hrow[c];
                const float h1 = hrow[c + 1];
                const unsigned long long hp0 = pack2(h0, h0);
                const unsigned long long hp1 = pack2(h1, h1);
                a0 = fma2(hp0, areg[c + 0][0], a0);
                a1 = fma2(hp0, areg[c + 0][1], a1);
                a2 = fma2(hp1, areg[c + 1][0], a2);
                a3 = fma2(hp1, areg[c + 1][1], a3);
            }
            const unsigned long long s01 = add2(a0, a2);
            const unsigned long long s23 = add2(a1, a3);
            float2 v0 = unpack2(s01);
            float2 v1 = unpack2(s23);
            float4 o;
            o.x = fmaxf(v0.x, 0.0f);
            o.y = fmaxf(v0.y, 0.0f);
            o.z = fmaxf(v1.x, 0.0f);
            o.w = fmaxf(v1.y, 0.0f);
            *(float4*)(obase + (size_t)rr * D_) = o;
        }
    }
}

extern "C" void kernel_launch(void* const* d_in, const int* in_sizes, int n_in,
                              void* d_out, int out_size) {
    const float* x = (const float*)d_in[0];
    const float* ab = (const float*)d_in[1];
    const float* aa = (const float*)d_in[2];
    float* out = (float*)d_out;

    lora_fused<<<(B_ * S_) / TILE_M, THREADS>>>(x, ab, aa, out);  // 512 CTAs
}